// round 1
// baseline (speedup 1.0000x reference)
#include <cuda_runtime.h>
#include <math.h>

// Shapes (fixed per reference): B=4, S=2048, H=2048, I=5504, E=8, R=16, top-k=2
#define S_LEN   2048
#define M_ROWS  8192            // B*S
#define I_DIM   5504
#define H_DIM   2048
#define LORA_SCALE 2.0f

// ---------------- scratch (device globals: alloc-free) ----------------
__device__ float g_gate[45088768];   // 8192*5504  (later reused as h)
__device__ float g_up  [45088768];   // 8192*5504
__device__ float g_u   [8192*64];    // [row][0:32]=gate lora u, [32:64]=up lora u
__device__ float g_v   [8192*32];    // down lora u
__device__ int   g_sel [8];          // per batch: 2 selected experts

// ---------------- top-2 gating ----------------
__global__ void topk_kernel(const float* __restrict__ gv) {
    int b = threadIdx.x;
    if (b >= 4) return;
    const float* r = gv + b * 8;
    int i0 = 0; float v0 = r[0];
    #pragma unroll
    for (int e = 1; e < 8; e++) if (r[e] > v0) { v0 = r[e]; i0 = e; }
    int i1 = -1; float v1 = -3.4e38f;
    #pragma unroll
    for (int e = 0; e < 8; e++) if (e != i0 && r[e] > v1) { v1 = r[e]; i1 = e; }
    g_sel[2*b]   = i0;
    g_sel[2*b+1] = i1;
}

// ---------------- U = X @ A_sel  (32 cols: 2 experts x r=16) ----------------
// X: [8192, K] row-major. A: (E, K, 16). Writes U[row*ustride + uoff + 0:32].
__global__ void lora_proj_kernel(const float* __restrict__ X,
                                 const float* __restrict__ A,
                                 int K, float* __restrict__ U,
                                 int ustride, int uoff)
{
    __shared__ float Xs[8][128];
    int tid  = threadIdx.x;
    int col  = tid & 31;          // 0..31
    int lr   = tid >> 5;          // 0..7 (local row)
    int row0 = blockIdx.x * 8;
    int b    = row0 >> 11;        // row / 2048
    int e    = g_sel[2*b + (col >> 4)];
    int r    = col & 15;
    const float* Ap = A + (size_t)e * K * 16 + r;

    float acc = 0.f;
    for (int k0 = 0; k0 < K; k0 += 128) {
        int flat = tid * 4;
        int rr = flat >> 7;
        int cc = flat & 127;
        *reinterpret_cast<float4*>(&Xs[rr][cc]) =
            *reinterpret_cast<const float4*>(X + (size_t)(row0 + rr) * K + k0 + cc);
        __syncthreads();
        #pragma unroll 8
        for (int kk = 0; kk < 128; kk++)
            acc += Xs[lr][kk] * Ap[(size_t)(k0 + kk) * 16];
        __syncthreads();
    }
    U[(size_t)(row0 + lr) * ustride + uoff + col] = acc;
}

// ---------------- 128x128x8 SGEMM + fused rank-32 LoRA epilogue ----------------
// C[m,n] = sum_k A[m,k]*W[n,k] + LORA_SCALE * sum_{r<32} U[m,r]*Bl[e(r), r%16, n]
__global__ void __launch_bounds__(256, 2)
gemm_lora_kernel(const float* __restrict__ A, const float* __restrict__ W,
                 const float* __restrict__ U, int ustride, int uoff,
                 const float* __restrict__ Bl,
                 float* __restrict__ C, int N, int K)
{
    __shared__ float smem[8448];
    float* As = smem;           // [8][128] k-major
    float* Bs = smem + 1024;    // [8][128]

    int tid = threadIdx.x;
    int tx = tid & 15, ty = tid >> 4;
    int row0 = blockIdx.y * 128;
    int col0 = blockIdx.x * 128;

    float acc[8][8];
    #pragma unroll
    for (int i = 0; i < 8; i++)
        #pragma unroll
        for (int j = 0; j < 8; j++) acc[i][j] = 0.f;

    int arow = tid >> 1;
    int ac4  = (tid & 1) * 4;
    const float* Aptr = A + (size_t)(row0 + arow) * K + ac4;
    const float* Wptr = W + (size_t)(col0 + arow) * K + ac4;

    for (int k0 = 0; k0 < K; k0 += 8) {
        float4 av = *reinterpret_cast<const float4*>(Aptr + k0);
        float4 wv = *reinterpret_cast<const float4*>(Wptr + k0);
        As[(ac4+0)*128 + arow] = av.x;
        As[(ac4+1)*128 + arow] = av.y;
        As[(ac4+2)*128 + arow] = av.z;
        As[(ac4+3)*128 + arow] = av.w;
        Bs[(ac4+0)*128 + arow] = wv.x;
        Bs[(ac4+1)*128 + arow] = wv.y;
        Bs[(ac4+2)*128 + arow] = wv.z;
        Bs[(ac4+3)*128 + arow] = wv.w;
        __syncthreads();
        #pragma unroll
        for (int k = 0; k < 8; k++) {
            float4 a0 = *reinterpret_cast<float4*>(&As[k*128 + ty*4]);
            float4 a1 = *reinterpret_cast<float4*>(&As[k*128 + 64 + ty*4]);
            float4 b0 = *reinterpret_cast<float4*>(&Bs[k*128 + tx*4]);
            float4 b1 = *reinterpret_cast<float4*>(&Bs[k*128 + 64 + tx*4]);
            float ra[8] = {a0.x,a0.y,a0.z,a0.w,a1.x,a1.y,a1.z,a1.w};
            float rb[8] = {b0.x,b0.y,b0.z,b0.w,b1.x,b1.y,b1.z,b1.w};
            #pragma unroll
            for (int i = 0; i < 8; i++)
                #pragma unroll
                for (int j = 0; j < 8; j++)
                    acc[i][j] += ra[i] * rb[j];
        }
        __syncthreads();
    }

    // --- LoRA rank-32 epilogue (reuse smem) ---
    int b  = row0 >> 11;
    int e0 = g_sel[2*b], e1 = g_sel[2*b+1];
    float* Us = smem;           // [128][33] padded
    float* Be = smem + 4224;    // [32][128]
    for (int idx = tid; idx < 128*32; idx += 256) {
        int rw = idx >> 5, r = idx & 31;
        Us[rw*33 + r] = U[(size_t)(row0 + rw) * ustride + uoff + r];
    }
    for (int idx = tid; idx < 32*128; idx += 256) {
        int r = idx >> 7, c = idx & 127;
        int e = (r < 16) ? e0 : e1;
        Be[r*128 + c] = LORA_SCALE * Bl[((size_t)e*16 + (r & 15)) * N + col0 + c];
    }
    __syncthreads();
    #pragma unroll 4
    for (int r = 0; r < 32; r++) {
        float ua[8];
        #pragma unroll
        for (int i = 0; i < 4; i++) {
            ua[i]   = Us[(ty*4 + i)*33 + r];
            ua[4+i] = Us[(64 + ty*4 + i)*33 + r];
        }
        float4 b0 = *reinterpret_cast<float4*>(&Be[r*128 + tx*4]);
        float4 b1 = *reinterpret_cast<float4*>(&Be[r*128 + 64 + tx*4]);
        float rb[8] = {b0.x,b0.y,b0.z,b0.w,b1.x,b1.y,b1.z,b1.w};
        #pragma unroll
        for (int i = 0; i < 8; i++)
            #pragma unroll
            for (int j = 0; j < 8; j++)
                acc[i][j] += ua[i] * rb[j];
    }

    // --- store ---
    #pragma unroll
    for (int i = 0; i < 8; i++) {
        int ri = (i < 4) ? (ty*4 + i) : (64 + ty*4 + (i - 4));
        float4 v0 = make_float4(acc[i][0], acc[i][1], acc[i][2], acc[i][3]);
        float4 v1 = make_float4(acc[i][4], acc[i][5], acc[i][6], acc[i][7]);
        *reinterpret_cast<float4*>(C + (size_t)(row0 + ri) * N + col0 + tx*4)      = v0;
        *reinterpret_cast<float4*>(C + (size_t)(row0 + ri) * N + col0 + 64 + tx*4) = v1;
    }
}

// ---------------- h = silu(gate) * up (in place over gate) ----------------
__global__ void silu_mul_kernel(float* __restrict__ gate, const float* __restrict__ up, int n4)
{
    int i = blockIdx.x * blockDim.x + threadIdx.x;
    if (i >= n4) return;
    float4 g = reinterpret_cast<float4*>(gate)[i];
    float4 u = reinterpret_cast<const float4*>(up)[i];
    g.x = g.x / (1.f + expf(-g.x)) * u.x;
    g.y = g.y / (1.f + expf(-g.y)) * u.y;
    g.z = g.z / (1.f + expf(-g.z)) * u.z;
    g.w = g.w / (1.f + expf(-g.w)) * u.w;
    reinterpret_cast<float4*>(gate)[i] = g;
}

// ---------------- launch ----------------
extern "C" void kernel_launch(void* const* d_in, const int* in_sizes, int n_in,
                              void* d_out, int out_size)
{
    const float* x  = (const float*)d_in[0];
    const float* gv = (const float*)d_in[1];
    const float* Wg = (const float*)d_in[2];
    const float* Ag = (const float*)d_in[3];
    const float* Bg = (const float*)d_in[4];
    const float* Wu = (const float*)d_in[5];
    const float* Au = (const float*)d_in[6];
    const float* Bu = (const float*)d_in[7];
    const float* Wd = (const float*)d_in[8];
    const float* Ad = (const float*)d_in[9];
    const float* Bd = (const float*)d_in[10];
    float* out = (float*)d_out;

    float *gate, *up, *u, *v;
    cudaGetSymbolAddress((void**)&gate, g_gate);
    cudaGetSymbolAddress((void**)&up,   g_up);
    cudaGetSymbolAddress((void**)&u,    g_u);
    cudaGetSymbolAddress((void**)&v,    g_v);

    topk_kernel<<<1, 4>>>(gv);

    lora_proj_kernel<<<1024, 256>>>(x, Ag, H_DIM, u, 64, 0);
    lora_proj_kernel<<<1024, 256>>>(x, Au, H_DIM, u, 64, 32);

    dim3 blk(256);
    gemm_lora_kernel<<<dim3(I_DIM/128, M_ROWS/128), blk>>>(x, Wg, u, 64, 0,  Bg, gate, I_DIM, H_DIM);
    gemm_lora_kernel<<<dim3(I_DIM/128, M_ROWS/128), blk>>>(x, Wu, u, 64, 32, Bu, up,   I_DIM, H_DIM);

    silu_mul_kernel<<<(M_ROWS * I_DIM / 4 + 255) / 256, 256>>>(gate, up, M_ROWS * I_DIM / 4);

    lora_proj_kernel<<<1024, 256>>>(gate, Ad, I_DIM, v, 32, 0);

    gemm_lora_kernel<<<dim3(H_DIM/128, M_ROWS/128), blk>>>(gate, Wd, v, 32, 0, Bd, out, H_DIM, I_DIM);
}

// round 3
// speedup vs baseline: 3.5107x; 3.5107x over previous
#include <cuda_runtime.h>
#include <math.h>
#include <stdint.h>

// Shapes: B=4, S=2048, H=2048, I=5504, E=8, R=16, top-2
#define M_ROWS  8192
#define I_DIM   5504
#define H_DIM   2048

// ---------------- scratch ----------------
__device__ float g_gate[45088768];   // 8192*5504 (reused as h)
__device__ float g_up  [45088768];
__device__ float g_u   [8192*64];
__device__ float g_v   [8192*32];
__device__ int   g_sel [8];

// ---------------- helpers ----------------
__device__ __forceinline__ uint32_t smem_u32(const void* p) {
    uint32_t a;
    asm("{ .reg .u64 t; cvta.to.shared.u64 t, %1; cvt.u32.u64 %0, t; }" : "=r"(a) : "l"(p));
    return a;
}
__device__ __forceinline__ uint32_t f2tf(float x) {
    uint32_t r; asm("cvt.rna.tf32.f32 %0, %1;" : "=r"(r) : "f"(x)); return r;
}
__device__ __forceinline__ void sts128(uint32_t a, uint32_t x, uint32_t y, uint32_t z, uint32_t w) {
    asm volatile("st.shared.v4.b32 [%0], {%1,%2,%3,%4};" :: "r"(a), "r"(x), "r"(y), "r"(z), "r"(w) : "memory");
}
__device__ __forceinline__ void mma_tf32(float* c,
                                         uint32_t a0, uint32_t a1, uint32_t a2, uint32_t a3,
                                         uint32_t b0, uint32_t b1) {
    asm volatile(
        "mma.sync.aligned.m16n8k8.row.col.f32.tf32.tf32.f32 "
        "{%0,%1,%2,%3},{%4,%5,%6,%7},{%8,%9},{%0,%1,%2,%3};"
        : "+f"(c[0]), "+f"(c[1]), "+f"(c[2]), "+f"(c[3])
        : "r"(a0), "r"(a1), "r"(a2), "r"(a3), "r"(b0), "r"(b1));
}

// ---------------- top-2 gating ----------------
__global__ void topk_kernel(const float* __restrict__ gv) {
    int b = threadIdx.x;
    if (b >= 4) return;
    const float* r = gv + b * 8;
    int i0 = 0; float v0 = r[0];
    #pragma unroll
    for (int e = 1; e < 8; e++) if (r[e] > v0) { v0 = r[e]; i0 = e; }
    int i1 = -1; float v1 = -3.4e38f;
    #pragma unroll
    for (int e = 0; e < 8; e++) if (e != i0 && r[e] > v1) { v1 = r[e]; i1 = e; }
    g_sel[2*b] = i0; g_sel[2*b+1] = i1;
}

// ---------------- U = X @ A_sel (32 cols: 2 experts x r=16) ----------------
__global__ void lora_proj_kernel(const float* __restrict__ X,
                                 const float* __restrict__ A,
                                 int K, float* __restrict__ U,
                                 int ustride, int uoff)
{
    __shared__ float Xs[8][128];
    int tid = threadIdx.x;
    int col = tid & 31, lr = tid >> 5;
    int row0 = blockIdx.x * 8;
    int b = row0 >> 11;
    int e = g_sel[2*b + (col >> 4)];
    int r = col & 15;
    const float* Ap = A + (size_t)e * K * 16 + r;

    float acc = 0.f;
    for (int k0 = 0; k0 < K; k0 += 128) {
        int flat = tid * 4;
        int rr = flat >> 7, cc = flat & 127;
        *reinterpret_cast<float4*>(&Xs[rr][cc]) =
            *reinterpret_cast<const float4*>(X + (size_t)(row0 + rr) * K + k0 + cc);
        __syncthreads();
        #pragma unroll 8
        for (int kk = 0; kk < 128; kk++)
            acc += Xs[lr][kk] * Ap[(size_t)(k0 + kk) * 16];
        __syncthreads();
    }
    U[(size_t)(row0 + lr) * ustride + uoff + col] = acc;
}

// ---------------- tf32 mma.sync GEMM, LoRA folded as augmented K-chunk ----------------
// C[128x128 tile] = A[128,K] @ W[128,K]^T + U[128,32] @ (2*Bl_sel)[32,128]
// SMEM layout: [row][k] with stride 36 floats (bank-conflict-free fragments).
#define SSTRIDE 36
#define BUF_U32 (128 * SSTRIDE)           // 4608 u32 per matrix

__global__ void __launch_bounds__(256, 2)
gemm_mma_kernel(const float* __restrict__ A, const float* __restrict__ W,
                const float* __restrict__ U, int ustride, int uoff,
                const float* __restrict__ Bl,
                float* __restrict__ C, int N, int K)
{
    extern __shared__ uint32_t smem_u[];

    int tid  = threadIdx.x;
    int wid  = tid >> 5, lane = tid & 31;
    int g    = lane >> 2, tig = lane & 3;
    int warp_m = (wid & 1) * 64;
    int warp_n = (wid >> 1) * 32;
    int row0 = blockIdx.y * 128, col0 = blockIdx.x * 128;
    int bb   = row0 >> 11;
    int e0 = g_sel[2*bb], e1 = g_sel[2*bb+1];

    float acc[4][4][4];
    #pragma unroll
    for (int i = 0; i < 4; i++)
        #pragma unroll
        for (int j = 0; j < 4; j++)
            #pragma unroll
            for (int q = 0; q < 4; q++) acc[i][j][q] = 0.f;

    // global-load assignment: 2 threads per row, 16 floats each
    int lr = tid >> 1;
    int cf = (tid & 1) << 4;
    const float* aptr = A + (size_t)(row0 + lr) * K + cf;
    const float* wptr = W + (size_t)(col0 + lr) * K + cf;
    uint32_t sbyte = (uint32_t)(lr * SSTRIDE + cf) * 4u;   // byte offset in a matrix buffer
    uint32_t smem_base = smem_u32(smem_u);

    int nk = K >> 5;
    int ntot = nk + 1;

    float4 pa[4], pb[4];

    auto loadA = [&](int i) {
        if (i < nk) {
            const float4* s = reinterpret_cast<const float4*>(aptr + (i << 5));
            pa[0] = s[0]; pa[1] = s[1]; pa[2] = s[2]; pa[3] = s[3];
        } else {
            const float4* s = reinterpret_cast<const float4*>(U + (size_t)(row0 + lr) * ustride + uoff + cf);
            pa[0] = s[0]; pa[1] = s[1]; pa[2] = s[2]; pa[3] = s[3];
        }
    };
    auto loadB = [&](int i) {
        if (i < nk) {
            const float4* s = reinterpret_cast<const float4*>(wptr + (i << 5));
            pb[0] = s[0]; pb[1] = s[1]; pb[2] = s[2]; pb[3] = s[3];
        } else {
            float* f = reinterpret_cast<float*>(pb);
            #pragma unroll
            for (int j = 0; j < 16; j++) {
                int k = cf + j;
                int e = (k < 16) ? e0 : e1;
                f[j] = 2.0f * Bl[((size_t)(e * 16 + (k & 15))) * N + col0 + lr];
            }
        }
    };
    auto stsA = [&](int buf, float4* p) {
        uint32_t base = smem_base + (uint32_t)buf * (2u * BUF_U32 * 4u) + sbyte;
        #pragma unroll
        for (int j = 0; j < 4; j++)
            sts128(base + j * 16u, f2tf(p[j].x), f2tf(p[j].y), f2tf(p[j].z), f2tf(p[j].w));
    };
    auto stsB = [&](int buf, float4* p) {
        uint32_t base = smem_base + (uint32_t)buf * (2u * BUF_U32 * 4u) + BUF_U32 * 4u + sbyte;
        #pragma unroll
        for (int j = 0; j < 4; j++)
            sts128(base + j * 16u, f2tf(p[j].x), f2tf(p[j].y), f2tf(p[j].z), f2tf(p[j].w));
    };
    auto compute_half = [&](const uint32_t* As_, const uint32_t* Ws_, int kk0) {
        #pragma unroll
        for (int h = 0; h < 2; h++) {
            int kk = kk0 + 8 * h;
            uint32_t b0[4], b1[4];
            #pragma unroll
            for (int nt = 0; nt < 4; nt++) {
                int n = warp_n + nt * 8 + g;
                b0[nt] = Ws_[n * SSTRIDE + kk + tig];
                b1[nt] = Ws_[n * SSTRIDE + kk + tig + 4];
            }
            #pragma unroll
            for (int mt = 0; mt < 4; mt++) {
                int m = warp_m + mt * 16 + g;
                uint32_t a0 = As_[m * SSTRIDE + kk + tig];
                uint32_t a1 = As_[(m + 8) * SSTRIDE + kk + tig];
                uint32_t a2 = As_[m * SSTRIDE + kk + tig + 4];
                uint32_t a3 = As_[(m + 8) * SSTRIDE + kk + tig + 4];
                #pragma unroll
                for (int nt = 0; nt < 4; nt++)
                    mma_tf32(acc[mt][nt], a0, a1, a2, a3, b0[nt], b1[nt]);
            }
        }
    };

    // prologue
    loadA(0); loadB(0);
    stsA(0, pa); stsB(0, pb);
    __syncthreads();

    for (int i = 0; i < ntot; i++) {
        int cur = i & 1, nxt = cur ^ 1;
        const uint32_t* As_ = smem_u + cur * 2 * BUF_U32;
        const uint32_t* Ws_ = As_ + BUF_U32;
        bool pf = (i + 1 < ntot);

        if (pf) loadA(i + 1);
        compute_half(As_, Ws_, 0);
        if (pf) stsA(nxt, pa);
        if (pf) loadB(i + 1);
        compute_half(As_, Ws_, 16);
        if (pf) stsB(nxt, pb);
        __syncthreads();
    }

    // store C
    #pragma unroll
    for (int mt = 0; mt < 4; mt++) {
        int m = row0 + warp_m + mt * 16 + g;
        #pragma unroll
        for (int nt = 0; nt < 4; nt++) {
            int n = col0 + warp_n + nt * 8 + tig * 2;
            float2* p0 = reinterpret_cast<float2*>(C + (size_t)m * N + n);
            float2* p1 = reinterpret_cast<float2*>(C + (size_t)(m + 8) * N + n);
            *p0 = make_float2(acc[mt][nt][0], acc[mt][nt][1]);
            *p1 = make_float2(acc[mt][nt][2], acc[mt][nt][3]);
        }
    }
}

// ---------------- h = silu(gate) * up ----------------
__global__ void silu_mul_kernel(float* __restrict__ gate, const float* __restrict__ up, int n4)
{
    int i = blockIdx.x * blockDim.x + threadIdx.x;
    if (i >= n4) return;
    float4 g = reinterpret_cast<float4*>(gate)[i];
    float4 u = reinterpret_cast<const float4*>(up)[i];
    g.x = g.x / (1.f + expf(-g.x)) * u.x;
    g.y = g.y / (1.f + expf(-g.y)) * u.y;
    g.z = g.z / (1.f + expf(-g.z)) * u.z;
    g.w = g.w / (1.f + expf(-g.w)) * u.w;
    reinterpret_cast<float4*>(gate)[i] = g;
}

// ---------------- launch ----------------
extern "C" void kernel_launch(void* const* d_in, const int* in_sizes, int n_in,
                              void* d_out, int out_size)
{
    const float* x  = (const float*)d_in[0];
    const float* gv = (const float*)d_in[1];
    const float* Wg = (const float*)d_in[2];
    const float* Ag = (const float*)d_in[3];
    const float* Bg = (const float*)d_in[4];
    const float* Wu = (const float*)d_in[5];
    const float* Au = (const float*)d_in[6];
    const float* Bu = (const float*)d_in[7];
    const float* Wd = (const float*)d_in[8];
    const float* Ad = (const float*)d_in[9];
    const float* Bd = (const float*)d_in[10];
    float* out = (float*)d_out;

    float *gate, *up, *u, *v;
    cudaGetSymbolAddress((void**)&gate, g_gate);
    cudaGetSymbolAddress((void**)&up,   g_up);
    cudaGetSymbolAddress((void**)&u,    g_u);
    cudaGetSymbolAddress((void**)&v,    g_v);

    const int DSMEM = 4 * BUF_U32 * 4;   // 73728 bytes: 2 buffers x (A+B)
    cudaFuncSetAttribute(gemm_mma_kernel, cudaFuncAttributeMaxDynamicSharedMemorySize, DSMEM);

    topk_kernel<<<1, 4>>>(gv);

    lora_proj_kernel<<<1024, 256>>>(x, Ag, H_DIM, u, 64, 0);
    lora_proj_kernel<<<1024, 256>>>(x, Au, H_DIM, u, 64, 32);

    gemm_mma_kernel<<<dim3(I_DIM/128, M_ROWS/128), 256, DSMEM>>>(x, Wg, u, 64, 0,  Bg, gate, I_DIM, H_DIM);
    gemm_mma_kernel<<<dim3(I_DIM/128, M_ROWS/128), 256, DSMEM>>>(x, Wu, u, 64, 32, Bu, up,   I_DIM, H_DIM);

    silu_mul_kernel<<<(M_ROWS * I_DIM / 4 + 255) / 256, 256>>>(gate, up, M_ROWS * I_DIM / 4);

    lora_proj_kernel<<<1024, 256>>>(gate, Ad, I_DIM, v, 32, 0);

    gemm_mma_kernel<<<dim3(H_DIM/128, M_ROWS/128), 256, DSMEM>>>(gate, Wd, v, 32, 0, Bd, out, H_DIM, I_DIM);
}

// round 4
// speedup vs baseline: 4.6088x; 1.3128x over previous
#include <cuda_runtime.h>
#include <math.h>
#include <stdint.h>

// Shapes: B=4, S=2048, H=2048, I=5504, E=8, R=16, top-2
#define M_ROWS  8192
#define I_DIM   5504
#define H_DIM   2048

#define BM 256
#define BN 128
#define BK 32
#define SSTRIDE 36
#define ABUF_U32 (BM * SSTRIDE)
#define BBUF_U32 (BN * SSTRIDE)
#define BUFPAIR_U32 (ABUF_U32 + BBUF_U32)

// ---------------- scratch ----------------
__device__ float g_gate[45088768];   // 8192*5504 (reused as h)
__device__ float g_up  [45088768];
__device__ float g_u   [8192*64];
__device__ float g_v   [8192*32];
__device__ int   g_sel [8];

// ---------------- helpers ----------------
__device__ __forceinline__ uint32_t smem_u32(const void* p) {
    uint32_t a;
    asm("{ .reg .u64 t; cvta.to.shared.u64 t, %1; cvt.u32.u64 %0, t; }" : "=r"(a) : "l"(p));
    return a;
}
__device__ __forceinline__ uint32_t f2tf(float x) {
    uint32_t r; asm("cvt.rna.tf32.f32 %0, %1;" : "=r"(r) : "f"(x)); return r;
}
__device__ __forceinline__ void sts128(uint32_t a, uint32_t x, uint32_t y, uint32_t z, uint32_t w) {
    asm volatile("st.shared.v4.b32 [%0], {%1,%2,%3,%4};" :: "r"(a), "r"(x), "r"(y), "r"(z), "r"(w) : "memory");
}
__device__ __forceinline__ void mma_tf32(float* c,
                                         uint32_t a0, uint32_t a1, uint32_t a2, uint32_t a3,
                                         uint32_t b0, uint32_t b1) {
    asm volatile(
        "mma.sync.aligned.m16n8k8.row.col.f32.tf32.tf32.f32 "
        "{%0,%1,%2,%3},{%4,%5,%6,%7},{%8,%9},{%0,%1,%2,%3};"
        : "+f"(c[0]), "+f"(c[1]), "+f"(c[2]), "+f"(c[3])
        : "r"(a0), "r"(a1), "r"(a2), "r"(a3), "r"(b0), "r"(b1));
}

// ---------------- top-2 gating ----------------
__global__ void topk_kernel(const float* __restrict__ gv) {
    int b = threadIdx.x;
    if (b >= 4) return;
    const float* r = gv + b * 8;
    int i0 = 0; float v0 = r[0];
    #pragma unroll
    for (int e = 1; e < 8; e++) if (r[e] > v0) { v0 = r[e]; i0 = e; }
    int i1 = -1; float v1 = -3.4e38f;
    #pragma unroll
    for (int e = 0; e < 8; e++) if (e != i0 && r[e] > v1) { v1 = r[e]; i1 = e; }
    g_sel[2*b] = i0; g_sel[2*b+1] = i1;
}

// ---------------- U = X @ A_sel (32 cols: 2 experts x r=16) ----------------
__global__ void lora_proj_kernel(const float* __restrict__ X,
                                 const float* __restrict__ A,
                                 int K, float* __restrict__ U,
                                 int ustride, int uoff)
{
    __shared__ float Xs[8][128];
    int tid = threadIdx.x;
    int col = tid & 31, lr = tid >> 5;
    int row0 = blockIdx.x * 8;
    int b = row0 >> 11;
    int e = g_sel[2*b + (col >> 4)];
    int r = col & 15;
    const float* Ap = A + (size_t)e * K * 16 + r;

    float acc = 0.f;
    for (int k0 = 0; k0 < K; k0 += 128) {
        int flat = tid * 4;
        int rr = flat >> 7, cc = flat & 127;
        *reinterpret_cast<float4*>(&Xs[rr][cc]) =
            *reinterpret_cast<const float4*>(X + (size_t)(row0 + rr) * K + k0 + cc);
        __syncthreads();
        #pragma unroll 8
        for (int kk = 0; kk < 128; kk++)
            acc += Xs[lr][kk] * Ap[(size_t)(k0 + kk) * 16];
        __syncthreads();
    }
    U[(size_t)(row0 + lr) * ustride + uoff + col] = acc;
}

// ---------------- tf32 mma.sync GEMM, 256x128 tile, 64x64 warp tiles ----------------
// C[256x128 tile] = A[256,K] @ W[128,K]^T + U[256,32] @ (2*Bl_sel)[32,128]
__global__ void __launch_bounds__(256, 1)
gemm_mma_kernel(const float* __restrict__ A, const float* __restrict__ W,
                const float* __restrict__ U, int ustride, int uoff,
                const float* __restrict__ Bl,
                float* __restrict__ C, int N, int K)
{
    extern __shared__ uint32_t smem_u[];

    int tid  = threadIdx.x;
    int wid  = tid >> 5, lane = tid & 31;
    int g    = lane >> 2, tig = lane & 3;
    int warp_m = (wid >> 1) * 64;        // 4 m-bands
    int warp_n = (wid & 1) * 64;         // 2 n-bands
    int row0 = blockIdx.y * BM, col0 = blockIdx.x * BN;
    int bb   = row0 >> 11;
    int e0 = g_sel[2*bb], e1 = g_sel[2*bb+1];

    float acc[4][8][4];
    #pragma unroll
    for (int i = 0; i < 4; i++)
        #pragma unroll
        for (int j = 0; j < 8; j++)
            #pragma unroll
            for (int q = 0; q < 4; q++) acc[i][j][q] = 0.f;

    // coalesced loader: 8 threads per row, float4 each
    int lr = tid >> 3;                   // 0..31
    int c4 = (tid & 7) << 2;             // 0,4,...,28
    uint32_t smem_base = smem_u32(smem_u);

    int nk = K >> 5;
    int ntot = nk + 1;

    float4 pa[8], pb[4];

    auto loadA = [&](int i) {
        if (i < nk) {
            int k0 = i << 5;
            #pragma unroll
            for (int j = 0; j < 8; j++)
                pa[j] = *reinterpret_cast<const float4*>(A + (size_t)(row0 + lr + 32*j) * K + k0 + c4);
        } else {
            #pragma unroll
            for (int j = 0; j < 8; j++)
                pa[j] = *reinterpret_cast<const float4*>(U + (size_t)(row0 + lr + 32*j) * ustride + uoff + c4);
        }
    };
    auto loadB = [&](int i) {
        if (i < nk) {
            int k0 = i << 5;
            #pragma unroll
            for (int j = 0; j < 4; j++)
                pb[j] = *reinterpret_cast<const float4*>(W + (size_t)(col0 + lr + 32*j) * K + k0 + c4);
        } else {
            #pragma unroll
            for (int j = 0; j < 4; j++) {
                int n = lr + 32*j;
                float* f = reinterpret_cast<float*>(&pb[j]);
                #pragma unroll
                for (int t = 0; t < 4; t++) {
                    int k = c4 + t;
                    int e = (k < 16) ? e0 : e1;
                    f[t] = 2.0f * Bl[((size_t)(e * 16 + (k & 15))) * N + col0 + n];
                }
            }
        }
    };
    auto stsA = [&](int buf) {
        uint32_t base = smem_base + (uint32_t)buf * (BUFPAIR_U32 * 4u);
        #pragma unroll
        for (int j = 0; j < 8; j++) {
            uint32_t a = base + (uint32_t)((lr + 32*j) * SSTRIDE + c4) * 4u;
            sts128(a, f2tf(pa[j].x), f2tf(pa[j].y), f2tf(pa[j].z), f2tf(pa[j].w));
        }
    };
    auto stsB = [&](int buf) {
        uint32_t base = smem_base + (uint32_t)buf * (BUFPAIR_U32 * 4u) + ABUF_U32 * 4u;
        #pragma unroll
        for (int j = 0; j < 4; j++) {
            uint32_t a = base + (uint32_t)((lr + 32*j) * SSTRIDE + c4) * 4u;
            sts128(a, f2tf(pb[j].x), f2tf(pb[j].y), f2tf(pb[j].z), f2tf(pb[j].w));
        }
    };
    auto compute_half = [&](const uint32_t* As_, const uint32_t* Ws_, int kk0) {
        #pragma unroll
        for (int h = 0; h < 2; h++) {
            int kk = kk0 + 8 * h;
            uint32_t b0[8], b1[8];
            #pragma unroll
            for (int nt = 0; nt < 8; nt++) {
                int n = warp_n + nt * 8 + g;
                b0[nt] = Ws_[n * SSTRIDE + kk + tig];
                b1[nt] = Ws_[n * SSTRIDE + kk + tig + 4];
            }
            #pragma unroll
            for (int mt = 0; mt < 4; mt++) {
                int m = warp_m + mt * 16 + g;
                uint32_t a0 = As_[m * SSTRIDE + kk + tig];
                uint32_t a1 = As_[(m + 8) * SSTRIDE + kk + tig];
                uint32_t a2 = As_[m * SSTRIDE + kk + tig + 4];
                uint32_t a3 = As_[(m + 8) * SSTRIDE + kk + tig + 4];
                #pragma unroll
                for (int nt = 0; nt < 8; nt++)
                    mma_tf32(acc[mt][nt], a0, a1, a2, a3, b0[nt], b1[nt]);
            }
        }
    };

    // prologue
    loadA(0); loadB(0);
    stsA(0); stsB(0);
    __syncthreads();

    for (int i = 0; i < ntot; i++) {
        int cur = i & 1, nxt = cur ^ 1;
        const uint32_t* As_ = smem_u + cur * BUFPAIR_U32;
        const uint32_t* Ws_ = As_ + ABUF_U32;
        bool pf = (i + 1 < ntot);

        if (pf) loadA(i + 1);
        compute_half(As_, Ws_, 0);
        if (pf) stsA(nxt);
        if (pf) loadB(i + 1);
        compute_half(As_, Ws_, 16);
        if (pf) stsB(nxt);
        __syncthreads();
    }

    // store C
    #pragma unroll
    for (int mt = 0; mt < 4; mt++) {
        int m = row0 + warp_m + mt * 16 + g;
        #pragma unroll
        for (int nt = 0; nt < 8; nt++) {
            int n = col0 + warp_n + nt * 8 + tig * 2;
            float2* p0 = reinterpret_cast<float2*>(C + (size_t)m * N + n);
            float2* p1 = reinterpret_cast<float2*>(C + (size_t)(m + 8) * N + n);
            *p0 = make_float2(acc[mt][nt][0], acc[mt][nt][1]);
            *p1 = make_float2(acc[mt][nt][2], acc[mt][nt][3]);
        }
    }
}

// ---------------- h = silu(gate) * up ----------------
__global__ void silu_mul_kernel(float* __restrict__ gate, const float* __restrict__ up, int n4)
{
    int i = blockIdx.x * blockDim.x + threadIdx.x;
    if (i >= n4) return;
    float4 g = reinterpret_cast<float4*>(gate)[i];
    float4 u = reinterpret_cast<const float4*>(up)[i];
    g.x = g.x / (1.f + expf(-g.x)) * u.x;
    g.y = g.y / (1.f + expf(-g.y)) * u.y;
    g.z = g.z / (1.f + expf(-g.z)) * u.z;
    g.w = g.w / (1.f + expf(-g.w)) * u.w;
    reinterpret_cast<float4*>(gate)[i] = g;
}

// ---------------- launch ----------------
extern "C" void kernel_launch(void* const* d_in, const int* in_sizes, int n_in,
                              void* d_out, int out_size)
{
    const float* x  = (const float*)d_in[0];
    const float* gv = (const float*)d_in[1];
    const float* Wg = (const float*)d_in[2];
    const float* Ag = (const float*)d_in[3];
    const float* Bg = (const float*)d_in[4];
    const float* Wu = (const float*)d_in[5];
    const float* Au = (const float*)d_in[6];
    const float* Bu = (const float*)d_in[7];
    const float* Wd = (const float*)d_in[8];
    const float* Ad = (const float*)d_in[9];
    const float* Bd = (const float*)d_in[10];
    float* out = (float*)d_out;

    float *gate, *up, *u, *v;
    cudaGetSymbolAddress((void**)&gate, g_gate);
    cudaGetSymbolAddress((void**)&up,   g_up);
    cudaGetSymbolAddress((void**)&u,    g_u);
    cudaGetSymbolAddress((void**)&v,    g_v);

    const int DSMEM = 2 * BUFPAIR_U32 * 4;   // 110592 bytes
    cudaFuncSetAttribute(gemm_mma_kernel, cudaFuncAttributeMaxDynamicSharedMemorySize, DSMEM);

    topk_kernel<<<1, 4>>>(gv);

    lora_proj_kernel<<<1024, 256>>>(x, Ag, H_DIM, u, 64, 0);
    lora_proj_kernel<<<1024, 256>>>(x, Au, H_DIM, u, 64, 32);

    gemm_mma_kernel<<<dim3(I_DIM/BN, M_ROWS/BM), 256, DSMEM>>>(x, Wg, u, 64, 0,  Bg, gate, I_DIM, H_DIM);
    gemm_mma_kernel<<<dim3(I_DIM/BN, M_ROWS/BM), 256, DSMEM>>>(x, Wu, u, 64, 32, Bu, up,   I_DIM, H_DIM);

    silu_mul_kernel<<<(M_ROWS * I_DIM / 4 + 255) / 256, 256>>>(gate, up, M_ROWS * I_DIM / 4);

    lora_proj_kernel<<<1024, 256>>>(gate, Ad, I_DIM, v, 32, 0);

    gemm_mma_kernel<<<dim3(H_DIM/BN, M_ROWS/BM), 256, DSMEM>>>(gate, Wd, v, 32, 0, Bd, out, H_DIM, I_DIM);
}

// round 6
// speedup vs baseline: 5.3544x; 1.1618x over previous
#include <cuda_runtime.h>
#include <math.h>
#include <stdint.h>

// Shapes: B=4, S=2048, H=2048, I=5504, E=8, R=16, top-2
#define M_ROWS  8192
#define I_DIM   5504
#define H_DIM   2048

#define BM 256
#define BN 128
#define BK 32
#define NSTAGE 4
#define ABYTES (BM * 128)            // 32768
#define BBYTES (BN * 128)            // 16384
#define PAIRBYTES (ABYTES + BBYTES)  // 49152
#define AWORDS (ABYTES / 4)          // 8192
#define PAIRWORDS (PAIRBYTES / 4)    // 12288
#define DSMEM (NSTAGE * PAIRBYTES)   // 196608

// ---------------- scratch ----------------
__device__ float g_gate[45088768];   // 8192*5504 (reused as tf32-rounded h)
__device__ float g_up  [45088768];
__device__ float g_xc  [16777216];   // tf32-rounded x
__device__ float g_wgc [11272192];   // tf32-rounded Wg
__device__ float g_wuc [11272192];
__device__ float g_wdc [11272192];
__device__ float g_u   [8192*64];
__device__ float g_v   [8192*32];
__device__ int   g_sel [8];

// ---------------- helpers ----------------
__device__ __forceinline__ uint32_t smem_u32(const void* p) {
    uint32_t a;
    asm("{ .reg .u64 t; cvta.to.shared.u64 t, %1; cvt.u32.u64 %0, t; }" : "=r"(a) : "l"(p));
    return a;
}
__device__ __forceinline__ uint32_t f2tf(float x) {
    uint32_t r; asm("cvt.rna.tf32.f32 %0, %1;" : "=r"(r) : "f"(x)); return r;
}
__device__ __forceinline__ void sts128(uint32_t a, uint32_t x, uint32_t y, uint32_t z, uint32_t w) {
    asm volatile("st.shared.v4.b32 [%0], {%1,%2,%3,%4};" :: "r"(a), "r"(x), "r"(y), "r"(z), "r"(w) : "memory");
}
__device__ __forceinline__ void cpasync16(uint32_t dst, const void* src) {
    asm volatile("cp.async.cg.shared.global [%0], [%1], 16;" :: "r"(dst), "l"(src) : "memory");
}
__device__ __forceinline__ void cp_commit() {
    asm volatile("cp.async.commit_group;" ::: "memory");
}
template<int N>
__device__ __forceinline__ void cp_wait() {
    asm volatile("cp.async.wait_group %0;" :: "n"(N) : "memory");
}
__device__ __forceinline__ void mma_tf32(float* c,
                                         uint32_t a0, uint32_t a1, uint32_t a2, uint32_t a3,
                                         uint32_t b0, uint32_t b1) {
    asm volatile(
        "mma.sync.aligned.m16n8k8.row.col.f32.tf32.tf32.f32 "
        "{%0,%1,%2,%3},{%4,%5,%6,%7},{%8,%9},{%0,%1,%2,%3};"
        : "+f"(c[0]), "+f"(c[1]), "+f"(c[2]), "+f"(c[3])
        : "r"(a0), "r"(a1), "r"(a2), "r"(a3), "r"(b0), "r"(b1));
}

// ---------------- tf32 rounding pass ----------------
__global__ void cvt_tf32_kernel(const float* __restrict__ in, float* __restrict__ out, int n4)
{
    int i = blockIdx.x * blockDim.x + threadIdx.x;
    if (i >= n4) return;
    float4 v = reinterpret_cast<const float4*>(in)[i];
    uint4 o = make_uint4(f2tf(v.x), f2tf(v.y), f2tf(v.z), f2tf(v.w));
    reinterpret_cast<uint4*>(out)[i] = o;
}

// ---------------- top-2 gating ----------------
__global__ void topk_kernel(const float* __restrict__ gv) {
    int b = threadIdx.x;
    if (b >= 4) return;
    const float* r = gv + b * 8;
    int i0 = 0; float v0 = r[0];
    #pragma unroll
    for (int e = 1; e < 8; e++) if (r[e] > v0) { v0 = r[e]; i0 = e; }
    int i1 = -1; float v1 = -3.4e38f;
    #pragma unroll
    for (int e = 0; e < 8; e++) if (e != i0 && r[e] > v1) { v1 = r[e]; i1 = e; }
    g_sel[2*b] = i0; g_sel[2*b+1] = i1;
}

// ---------------- U = X @ A_sel (32 cols: 2 experts x r=16) ----------------
__global__ void lora_proj_kernel(const float* __restrict__ X,
                                 const float* __restrict__ A,
                                 int K, float* __restrict__ U,
                                 int ustride, int uoff)
{
    __shared__ float Xs[8][128];
    int tid = threadIdx.x;
    int col = tid & 31, lr = tid >> 5;
    int row0 = blockIdx.x * 8;
    int b = row0 >> 11;
    int e = g_sel[2*b + (col >> 4)];
    int r = col & 15;
    const float* Ap = A + (size_t)e * K * 16 + r;

    float acc = 0.f;
    for (int k0 = 0; k0 < K; k0 += 128) {
        int flat = tid * 4;
        int rr = flat >> 7, cc = flat & 127;
        *reinterpret_cast<float4*>(&Xs[rr][cc]) =
            *reinterpret_cast<const float4*>(X + (size_t)(row0 + rr) * K + k0 + cc);
        __syncthreads();
        #pragma unroll 8
        for (int kk = 0; kk < 128; kk++)
            acc += Xs[lr][kk] * Ap[(size_t)(k0 + kk) * 16];
        __syncthreads();
    }
    U[(size_t)(row0 + lr) * ustride + uoff + col] = acc;
}

// ---------------- tf32 mma.sync GEMM, cp.async 4-stage, 256x128 tile ----------------
// A, W pre-rounded to tf32. C = A @ W^T + U @ (2*Bl_sel)
__global__ void __launch_bounds__(256, 1)
gemm_mma_kernel(const float* __restrict__ A, const float* __restrict__ W,
                const float* __restrict__ U, int ustride, int uoff,
                const float* __restrict__ Bl,
                float* __restrict__ C, int N, int K)
{
    extern __shared__ __align__(128) uint32_t smem_u[];
    uint32_t smem_base = smem_u32(smem_u);

    int tid  = threadIdx.x;
    int wid  = tid >> 5, lane = tid & 31;
    int g    = lane >> 2, tig = lane & 3;
    int warp_m = (wid >> 1) * 64;
    int warp_n = (wid & 1) * 64;
    int row0 = blockIdx.y * BM, col0 = blockIdx.x * BN;
    int bb   = row0 >> 11;
    int e0 = g_sel[2*bb], e1 = g_sel[2*bb+1];

    float acc[4][8][4];
    #pragma unroll
    for (int i = 0; i < 4; i++)
        #pragma unroll
        for (int j = 0; j < 8; j++)
            #pragma unroll
            for (int q = 0; q < 4; q++) acc[i][j][q] = 0.f;

    // loader geometry: 8 threads/row, 16B each
    int lr  = tid >> 3;                 // 0..31
    int seg = tid & 7;
    int c4  = seg << 2;
    // swizzled dst byte offsets (within a matrix region)
    uint32_t dstA[8], dstB[4];
    #pragma unroll
    for (int j = 0; j < 8; j++)
        dstA[j] = (uint32_t)((lr + 32*j) * 128 + 16 * (seg ^ (lr & 7)));
    #pragma unroll
    for (int j = 0; j < 4; j++)
        dstB[j] = (uint32_t)((lr + 32*j) * 128 + 16 * (seg ^ (lr & 7)));

    const float* aptr = A + (size_t)(row0 + lr) * K + c4;
    const float* wptr = W + (size_t)(col0 + lr) * K + c4;

    int nk = K >> 5;
    int ntot = nk + 1;

    auto issue_chunk = [&](int i) {
        int buf = i & (NSTAGE - 1);
        uint32_t a_s = smem_base + (uint32_t)buf * PAIRBYTES;
        uint32_t b_s = a_s + ABYTES;
        if (i < nk) {
            const float* ap = aptr + (i << 5);
            const float* wp = wptr + (i << 5);
            #pragma unroll
            for (int j = 0; j < 8; j++)
                cpasync16(a_s + dstA[j], ap + (size_t)(32 * j) * K);
            #pragma unroll
            for (int j = 0; j < 4; j++)
                cpasync16(b_s + dstB[j], wp + (size_t)(32 * j) * K);
        } else {
            // LoRA chunk: A-part = U[row, 0:32], B-part[n][k] = 2*Bl[e(k), k&15, col0+n]
            #pragma unroll
            for (int j = 0; j < 8; j++) {
                float4 uv = *reinterpret_cast<const float4*>(
                    U + (size_t)(row0 + lr + 32*j) * ustride + uoff + c4);
                sts128(a_s + dstA[j], f2tf(uv.x), f2tf(uv.y), f2tf(uv.z), f2tf(uv.w));
            }
            int e = (seg < 4) ? e0 : e1;
            #pragma unroll
            for (int j = 0; j < 4; j++) {
                int n = lr + 32*j;
                float f[4];
                #pragma unroll
                for (int t = 0; t < 4; t++) {
                    int k = c4 + t;
                    f[t] = 2.0f * Bl[((size_t)(e * 16 + (k & 15))) * N + col0 + n];
                }
                sts128(b_s + dstB[j], f2tf(f[0]), f2tf(f[1]), f2tf(f[2]), f2tf(f[3]));
            }
        }
        cp_commit();
    };

    // prologue: stages 0,1,2
    issue_chunk(0);
    issue_chunk(1);
    issue_chunk(2);

    int xr = 4 * g;   // fragment xor term (m&7 == g, n&7 == g)

    for (int i = 0; i < ntot; i++) {
        cp_wait<2>();
        __syncthreads();

        if (i + 3 < ntot) issue_chunk(i + 3);
        else cp_commit();   // keep group accounting uniform

        int buf = i & (NSTAGE - 1);
        const uint32_t* As_ = smem_u + buf * PAIRWORDS;
        const uint32_t* Ws_ = As_ + AWORDS;

        #pragma unroll
        for (int ks = 0; ks < 4; ks++) {
            int kk = ks << 3;
            int c_lo = (kk + tig) ^ xr;
            int c_hi = (kk + tig + 4) ^ xr;
            uint32_t b0[8], b1[8];
            #pragma unroll
            for (int nt = 0; nt < 8; nt++) {
                int n = warp_n + nt * 8 + g;
                b0[nt] = Ws_[n * 32 + c_lo];
                b1[nt] = Ws_[n * 32 + c_hi];
            }
            #pragma unroll
            for (int mt = 0; mt < 4; mt++) {
                int m = warp_m + mt * 16 + g;
                uint32_t a0 = As_[m * 32 + c_lo];
                uint32_t a1 = As_[(m + 8) * 32 + c_lo];
                uint32_t a2 = As_[m * 32 + c_hi];
                uint32_t a3 = As_[(m + 8) * 32 + c_hi];
                #pragma unroll
                for (int nt = 0; nt < 8; nt++)
                    mma_tf32(acc[mt][nt], a0, a1, a2, a3, b0[nt], b1[nt]);
            }
        }
        __syncthreads();
    }

    // store C
    #pragma unroll
    for (int mt = 0; mt < 4; mt++) {
        int m = row0 + warp_m + mt * 16 + g;
        #pragma unroll
        for (int nt = 0; nt < 8; nt++) {
            int n = col0 + warp_n + nt * 8 + tig * 2;
            float2* p0 = reinterpret_cast<float2*>(C + (size_t)m * N + n);
            float2* p1 = reinterpret_cast<float2*>(C + (size_t)(m + 8) * N + n);
            *p0 = make_float2(acc[mt][nt][0], acc[mt][nt][1]);
            *p1 = make_float2(acc[mt][nt][2], acc[mt][nt][3]);
        }
    }
}

// ---------------- h = tf32round(silu(gate) * up) ----------------
__global__ void silu_mul_kernel(float* __restrict__ gate, const float* __restrict__ up, int n4)
{
    int i = blockIdx.x * blockDim.x + threadIdx.x;
    if (i >= n4) return;
    float4 g = reinterpret_cast<float4*>(gate)[i];
    float4 u = reinterpret_cast<const float4*>(up)[i];
    uint4 o;
    o.x = f2tf(g.x / (1.f + expf(-g.x)) * u.x);
    o.y = f2tf(g.y / (1.f + expf(-g.y)) * u.y);
    o.z = f2tf(g.z / (1.f + expf(-g.z)) * u.z);
    o.w = f2tf(g.w / (1.f + expf(-g.w)) * u.w);
    reinterpret_cast<uint4*>(gate)[i] = o;
}

// ---------------- launch ----------------
extern "C" void kernel_launch(void* const* d_in, const int* in_sizes, int n_in,
                              void* d_out, int out_size)
{
    const float* x  = (const float*)d_in[0];
    const float* gv = (const float*)d_in[1];
    const float* Wg = (const float*)d_in[2];
    const float* Ag = (const float*)d_in[3];
    const float* Bg = (const float*)d_in[4];
    const float* Wu = (const float*)d_in[5];
    const float* Au = (const float*)d_in[6];
    const float* Bu = (const float*)d_in[7];
    const float* Wd = (const float*)d_in[8];
    const float* Ad = (const float*)d_in[9];
    const float* Bd = (const float*)d_in[10];
    float* out = (float*)d_out;

    float *gate, *up, *u, *v, *xc, *wgc, *wuc, *wdc;
    cudaGetSymbolAddress((void**)&gate, g_gate);
    cudaGetSymbolAddress((void**)&up,   g_up);
    cudaGetSymbolAddress((void**)&u,    g_u);
    cudaGetSymbolAddress((void**)&v,    g_v);
    cudaGetSymbolAddress((void**)&xc,   g_xc);
    cudaGetSymbolAddress((void**)&wgc,  g_wgc);
    cudaGetSymbolAddress((void**)&wuc,  g_wuc);
    cudaGetSymbolAddress((void**)&wdc,  g_wdc);

    cudaFuncSetAttribute(gemm_mma_kernel, cudaFuncAttributeMaxDynamicSharedMemorySize, DSMEM);

    topk_kernel<<<1, 4>>>(gv);

    // pre-round operands to tf32
    cvt_tf32_kernel<<<(16777216/4 + 255)/256, 256>>>(x,  xc,  16777216/4);
    cvt_tf32_kernel<<<(11272192/4 + 255)/256, 256>>>(Wg, wgc, 11272192/4);
    cvt_tf32_kernel<<<(11272192/4 + 255)/256, 256>>>(Wu, wuc, 11272192/4);
    cvt_tf32_kernel<<<(11272192/4 + 255)/256, 256>>>(Wd, wdc, 11272192/4);

    lora_proj_kernel<<<1024, 256>>>(x, Ag, H_DIM, u, 64, 0);
    lora_proj_kernel<<<1024, 256>>>(x, Au, H_DIM, u, 64, 32);

    gemm_mma_kernel<<<dim3(I_DIM/BN, M_ROWS/BM), 256, DSMEM>>>(xc, wgc, u, 64, 0,  Bg, gate, I_DIM, H_DIM);
    gemm_mma_kernel<<<dim3(I_DIM/BN, M_ROWS/BM), 256, DSMEM>>>(xc, wuc, u, 64, 32, Bu, up,   I_DIM, H_DIM);

    silu_mul_kernel<<<(M_ROWS * I_DIM / 4 + 255) / 256, 256>>>(gate, up, M_ROWS * I_DIM / 4);

    lora_proj_kernel<<<1024, 256>>>(gate, Ad, I_DIM, v, 32, 0);

    gemm_mma_kernel<<<dim3(H_DIM/BN, M_ROWS/BM), 256, DSMEM>>>(gate, wdc, v, 32, 0, Bd, out, H_DIM, I_DIM);
}